// round 3
// baseline (speedup 1.0000x reference)
#include <cuda_runtime.h>
#include <math_constants.h>

// ---------------------------------------------------------------------------
// DistillationLoss:
//   total = 1.0 * (0.7*chamfer(S,T) + 0.3*chamfer(S,G)) + 2.0 * edge_loss(S,F)
//   chamfer(a,b) = 0.5*(mean_i min_j |a_i-b_j| + mean_j min_i |a_i-b_j|)
//   edge_loss    = mean over 3*nF edges of squared edge length
//
// Strategy:
//   4 directed nearest-neighbor passes (S->T, T->S, S->G, G->S).
//   min over sqrt == sqrt of min over d2;  d2 = na + (nb - 2*a.b)
//   Inner loop per pair: 3 FFMA (dot) + 1 FFMA-imm + 1 FMNMX. B tiled in smem.
//   Per-query mins merged across B-chunks via uint atomicMin (d2 >= 0).
// ---------------------------------------------------------------------------

#define NN_TPB  256
#define NN_IPT  4
#define NN_TILE 256
#define NN_YSPLIT 6

__device__ float g_rowmin[48000];   // [S->T | T->S | S->G | G->S] min-d2 per query
__device__ float g_acc[8];          // 0..3: sum of min distances per pass, 4: edge sumsq

// ---------------------------------------------------------------------------
__global__ void init_kernel(int total_rowmin) {
    int i = blockIdx.x * blockDim.x + threadIdx.x;
    if (i < total_rowmin) g_rowmin[i] = CUDART_INF_F;
    if (i < 8) g_acc[i] = 0.0f;
}

// ---------------------------------------------------------------------------
// Directed NN: for each query a in A, min over b in [chunk] of (|b|^2 - 2 a.b),
// then d2 = max(|a|^2 + m, 0) -> atomicMin into g_rowmin[rowminOff + q].
__global__ void __launch_bounds__(NN_TPB)
nn_pass_kernel(const float* __restrict__ A, int nA,
               const float* __restrict__ B, int nB,
               int bChunk, int rowminOff) {
    __shared__ float4 sB[NN_TILE];
    const int tid = threadIdx.x;
    const int qBase = blockIdx.x * (NN_TPB * NN_IPT);

    float ax[NN_IPT], ay[NN_IPT], az[NN_IPT], m[NN_IPT];
#pragma unroll
    for (int k = 0; k < NN_IPT; ++k) {
        int q = qBase + tid + k * NN_TPB;
        if (q < nA) {
            ax[k] = A[3 * q + 0];
            ay[k] = A[3 * q + 1];
            az[k] = A[3 * q + 2];
        } else {
            ax[k] = 0.0f; ay[k] = 0.0f; az[k] = 0.0f;
        }
        m[k] = CUDART_INF_F;
    }

    const int b0 = blockIdx.y * bChunk;
    const int b1 = min(nB, b0 + bChunk);

    for (int jt = b0; jt < b1; jt += NN_TILE) {
        __syncthreads();
        int j = jt + tid;
        float4 v;
        if (j < b1) {
            float bx = B[3 * j + 0];
            float by = B[3 * j + 1];
            float bz = B[3 * j + 2];
            v = make_float4(bx, by, bz, fmaf(bx, bx, fmaf(by, by, bz * bz)));
        } else {
            // sentinel: never wins the min
            v = make_float4(0.0f, 0.0f, 0.0f, CUDART_INF_F);
        }
        sB[tid] = v;
        __syncthreads();

#pragma unroll 4
        for (int j2 = 0; j2 < NN_TILE; ++j2) {
            float4 bv = sB[j2];   // broadcast, conflict-free
#pragma unroll
            for (int k = 0; k < NN_IPT; ++k) {
                float dot = fmaf(ax[k], bv.x, fmaf(ay[k], bv.y, az[k] * bv.z));
                float t   = fmaf(dot, -2.0f, bv.w);   // |b|^2 - 2 a.b
                m[k] = fminf(m[k], t);
            }
        }
    }

#pragma unroll
    for (int k = 0; k < NN_IPT; ++k) {
        int q = qBase + tid + k * NN_TPB;
        if (q < nA) {
            float na = fmaf(ax[k], ax[k], fmaf(ay[k], ay[k], az[k] * az[k]));
            float d2 = fmaxf(na + m[k], 0.0f);   // >= 0 -> uint ordering valid
            atomicMin((unsigned int*)&g_rowmin[rowminOff + q], __float_as_uint(d2));
        }
    }
}

// ---------------------------------------------------------------------------
__device__ __forceinline__ float block_reduce_sum(float v) {
    __shared__ float sh[32];
    int lane = threadIdx.x & 31;
    int w = threadIdx.x >> 5;
#pragma unroll
    for (int o = 16; o; o >>= 1) v += __shfl_down_sync(0xffffffffu, v, o);
    if (lane == 0) sh[w] = v;
    __syncthreads();
    int nw = blockDim.x >> 5;
    v = (threadIdx.x < nw) ? sh[threadIdx.x] : 0.0f;
    if (w == 0) {
#pragma unroll
        for (int o = 16; o; o >>= 1) v += __shfl_down_sync(0xffffffffu, v, o);
    }
    return v;
}

// ---------------------------------------------------------------------------
// Edge loss: sum over faces of |v0-v1|^2 + |v1-v2|^2 + |v2-v0|^2  -> g_acc[4]
__global__ void edge_kernel(const float* __restrict__ V,
                            const int* __restrict__ F, int nF) {
    int f = blockIdx.x * blockDim.x + threadIdx.x;
    float s = 0.0f;
    if (f < nF) {
        int i0 = F[3 * f + 0];
        int i1 = F[3 * f + 1];
        int i2 = F[3 * f + 2];
        float x0 = V[3 * i0], y0 = V[3 * i0 + 1], z0 = V[3 * i0 + 2];
        float x1 = V[3 * i1], y1 = V[3 * i1 + 1], z1 = V[3 * i1 + 2];
        float x2 = V[3 * i2], y2 = V[3 * i2 + 1], z2 = V[3 * i2 + 2];
        float dx, dy, dz;
        dx = x0 - x1; dy = y0 - y1; dz = z0 - z1;
        s += fmaf(dx, dx, fmaf(dy, dy, dz * dz));
        dx = x1 - x2; dy = y1 - y2; dz = z1 - z2;
        s += fmaf(dx, dx, fmaf(dy, dy, dz * dz));
        dx = x2 - x0; dy = y2 - y0; dz = z2 - z0;
        s += fmaf(dx, dx, fmaf(dy, dy, dz * dz));
    }
    float bs = block_reduce_sum(s);
    if (threadIdx.x == 0) atomicAdd(&g_acc[4], bs);
}

// ---------------------------------------------------------------------------
// sqrt + segmented sum of the 4 rowmin arrays -> g_acc[0..3]
__global__ void sqrt_sum_kernel(int nS, int nT, int nG) {
    int seg = blockIdx.y;
    int off, len;
    if (seg == 0)      { off = 0;            len = nS; }
    else if (seg == 1) { off = nS;           len = nT; }
    else if (seg == 2) { off = nS + nT;      len = nS; }
    else               { off = 2 * nS + nT;  len = nG; }
    int i = blockIdx.x * blockDim.x + threadIdx.x;
    float v = 0.0f;
    if (i < len) v = sqrtf(g_rowmin[off + i]);
    float bs = block_reduce_sum(v);
    if (threadIdx.x == 0 && bs != 0.0f) atomicAdd(&g_acc[seg], bs);
}

// ---------------------------------------------------------------------------
__global__ void combine_kernel(float* out, int nS, int nT, int nG, int nF) {
    float lt = 0.5f * (g_acc[0] / (float)nS + g_acc[1] / (float)nT);
    float lg = 0.5f * (g_acc[2] / (float)nS + g_acc[3] / (float)nG);
    float le = g_acc[4] / (3.0f * (float)nF);
    out[0] = 0.7f * lt + 0.3f * lg + 2.0f * le;
}

// ---------------------------------------------------------------------------
extern "C" void kernel_launch(void* const* d_in, const int* in_sizes, int n_in,
                              void* d_out, int out_size) {
    const float* S = (const float*)d_in[0];
    const float* T = (const float*)d_in[1];
    const float* G = (const float*)d_in[2];
    const int*   F = (const int*)d_in[3];
    float* out = (float*)d_out;

    int nS = in_sizes[0] / 3;
    int nT = in_sizes[1] / 3;
    int nG = in_sizes[2] / 3;
    int nF = in_sizes[3] / 3;

    int totalRow = 2 * nS + nT + nG;
    init_kernel<<<(totalRow + 255) / 256, 256>>>(totalRow);

    // 4 directed NN passes
    {
        const int qspan = NN_TPB * NN_IPT;
        // S -> T
        {
            int qb = (nS + qspan - 1) / qspan;
            int chunk = (nT + NN_YSPLIT - 1) / NN_YSPLIT;
            nn_pass_kernel<<<dim3(qb, NN_YSPLIT), NN_TPB>>>(S, nS, T, nT, chunk, 0);
        }
        // T -> S
        {
            int qb = (nT + qspan - 1) / qspan;
            int chunk = (nS + NN_YSPLIT - 1) / NN_YSPLIT;
            nn_pass_kernel<<<dim3(qb, NN_YSPLIT), NN_TPB>>>(T, nT, S, nS, chunk, nS);
        }
        // S -> G
        {
            int qb = (nS + qspan - 1) / qspan;
            int chunk = (nG + NN_YSPLIT - 1) / NN_YSPLIT;
            nn_pass_kernel<<<dim3(qb, NN_YSPLIT), NN_TPB>>>(S, nS, G, nG, chunk, nS + nT);
        }
        // G -> S
        {
            int qb = (nG + qspan - 1) / qspan;
            int chunk = (nS + NN_YSPLIT - 1) / NN_YSPLIT;
            nn_pass_kernel<<<dim3(qb, NN_YSPLIT), NN_TPB>>>(G, nG, S, nS, chunk, 2 * nS + nT);
        }
    }

    edge_kernel<<<(nF + 255) / 256, 256>>>(S, F, nF);

    int maxLen = nS > nT ? nS : nT;
    if (nG > maxLen) maxLen = nG;
    sqrt_sum_kernel<<<dim3((maxLen + 255) / 256, 4), 256>>>(nS, nT, nG);

    combine_kernel<<<1, 1>>>(out, nS, nT, nG, nF);
}